// round 8
// baseline (speedup 1.0000x reference)
#include <cuda_runtime.h>

typedef unsigned long long u64;

#define HW   64
#define F    64
#define D    75
#define KR   5
#define SXW  68
#define NROW 15
#define NTHR 128

// f32 offsets
#define WLIN  0          // padded W [64][77] = 4928 f32 (dead after transpose)
#define WLO   4928       // [75][33] f32
#define WHI   7403       // [75][33] f32
#define X2F   11920      // 64 f32
#define FLO   0          // Slo [64][33] f32 (aliases WLIN)
#define FHI   2112       // Shi [64][33] f32 (aliases WLIN)
// u64 offsets
#define XPU   4940       // patch dup [15][68] u64 = 1020
#define W2U   5992       // w2 pairs: 32 u64
#define SWU   6024       // w2 partials [4][32] u64
#define SMEM_U64 6152    // 49216 B

__global__ __launch_bounds__(NTHR, 4)
void euclid2d_kernel(const float* __restrict__ x,
                     const float* __restrict__ W,
                     float* __restrict__ out) {
    __shared__ __align__(16) u64 S[SMEM_U64];
    float* Sf = (float*)S;

    const int tid  = threadIdx.x;
    const int lane = tid & 31;
    const int w    = tid >> 5;          // warp 0..3 -> pixels w*16..
    const int ho   = blockIdx.x;
    const int n    = blockIdx.y;

    // ---- phase A: coalesced W load -> padded rows [64][77] ----
    {
        const float4* src = (const float4*)W;
        #pragma unroll
        for (int k = 0; k < 10; k++) {
            int j = tid + k * NTHR;          // 1200 float4
            if (j < 1200) {
                float4 v = src[j];
                int b = 4 * j;
                Sf[WLIN + ((b    ) / D) * 77 + (b    ) % D] = v.x;
                Sf[WLIN + ((b + 1) / D) * 77 + (b + 1) % D] = v.y;
                Sf[WLIN + ((b + 2) / D) * 77 + (b + 2) % D] = v.z;
                Sf[WLIN + ((b + 3) / D) * 77 + (b + 3) % D] = v.w;
            }
        }
    }
    // ---- patch tile (duplicated pairs) ----
    {
        const int y0 = ho - 2;
        #pragma unroll
        for (int k = 0; k < 8; k++) {
            int i = tid + k * NTHR;          // 0..1019
            if (i < NROW * SXW) {
                int row = i / SXW;
                int col = i % SXW;
                int gy = y0 + (row % KR);
                int gx = col - 2;
                float v = 0.0f;
                if (gy >= 0 && gy < HW && gx >= 0 && gx < HW)
                    v = x[((n * 3 + (row / KR)) * HW + gy) * HW + gx];
                u64 p;
                asm("mov.b64 %0, {%1, %1};" : "=l"(p) : "f"(v));
                S[XPU + i] = p;
            }
        }
    }
    __syncthreads();

    // ---- phase B: conflict-free transpose into WLO/WHI (stride-33 rows) ----
    #pragma unroll
    for (int k = 0; k < 19; k++) {
        int idx = tid + k * NTHR;            // fp*75 + d ordering
        if (idx < 32 * D) {
            int fp = idx / D;
            int d  = idx % D;
            Sf[WLO + d * 33 + fp] = Sf[WLIN + (2 * fp)     * 77 + d];
            Sf[WHI + d * 33 + fp] = Sf[WLIN + (2 * fp + 1) * 77 + d];
        }
    }
    // ---- x2: 2 threads per pixel ----
    {
        const int p = tid >> 1;
        const int q = tid & 1;
        float s = 0.0f;
        #pragma unroll
        for (int k = 0; k < 38; k++) {
            int d = q + 2 * k;
            if (d < D) {
                int row = d / KR, kw = d % KR;
                float v = Sf[(XPU + row * SXW + p + kw) * 2];
                s += v * v;
            }
        }
        s += __shfl_xor_sync(0xffffffffu, s, 1);
        if (q == 0) Sf[X2F + p] = s;
    }
    __syncthreads();

    // ---- phase C: w2 pairs (4-way d-split; warp-uniform d -> conflict-free) ----
    {
        int fp = tid & 31, q = tid >> 5;
        u64 a = 0ULL;
        #pragma unroll
        for (int k = 0; k < 19; k++) {
            int d = q + 4 * k;
            if (d < D) {
                float lo = Sf[WLO + d * 33 + fp];
                float hi = Sf[WHI + d * 33 + fp];
                u64 wv;
                asm("mov.b64 %0, {%1, %2};" : "=l"(wv) : "f"(lo), "f"(hi));
                asm("fma.rn.f32x2 %0, %1, %1, %0;" : "+l"(a) : "l"(wv));
            }
        }
        S[SWU + q * 32 + fp] = a;
    }
    __syncthreads();
    if (tid < 32) {
        u64 a = S[SWU + tid], b = S[SWU + 32 + tid];
        u64 c = S[SWU + 64 + tid], d = S[SWU + 96 + tid];
        u64 r;
        asm("add.rn.f32x2 %0, %1, %2;" : "=l"(r) : "l"(a), "l"(b));
        asm("add.rn.f32x2 %0, %0, %1;" : "+l"(r) : "l"(c));
        asm("add.rn.f32x2 %0, %0, %1;" : "+l"(r) : "l"(d));
        S[W2U + tid] = r;
    }
    __syncthreads();

    // ---- main loop: lane = filter pair, thread = 16 pixels ----
    u64 acc[16];
    #pragma unroll
    for (int p = 0; p < 16; p++) acc[p] = 0ULL;

    #pragma unroll 1
    for (int row = 0; row < NROW; row++) {
        const ulonglong2* prow = (const ulonglong2*)&S[XPU + row * SXW + w * 16];
        ulonglong2 P2[10];
        #pragma unroll
        for (int t = 0; t < 10; t++) P2[t] = prow[t];      // broadcast LDS.128
        const u64* Pu = (const u64*)P2;
        #pragma unroll
        for (int kw = 0; kw < KR; kw++) {
            const int d = row * KR + kw;
            float wl = Sf[WLO + d * 33 + lane];            // conflict-free LDS.32
            float wh = Sf[WHI + d * 33 + lane];
            u64 wv;
            asm("mov.b64 %0, {%1, %2};" : "=l"(wv) : "f"(wl), "f"(wh));
            #pragma unroll
            for (int p = 0; p < 16; p++)
                asm("fma.rn.f32x2 %0, %1, %2, %0;"
                    : "+l"(acc[p]) : "l"(Pu[kw + p]), "l"(wv));
        }
    }

    // ---- epilogue: res = acc - 0.5*(x2+w2); padded Slo/Shi (alias WLIN) ----
    {
        u64 w2l = S[W2U + lane];
        u64 nh;
        { float mh = -0.5f; asm("mov.b64 %0, {%1, %1};" : "=l"(nh) : "f"(mh)); }
        #pragma unroll
        for (int p = 0; p < 16; p++) {
            int pix = w * 16 + p;
            float x2 = Sf[X2F + pix];
            u64 x2d, s, r = acc[p];
            asm("mov.b64 %0, {%1, %1};" : "=l"(x2d) : "f"(x2));
            asm("add.rn.f32x2 %0, %1, %2;" : "=l"(s) : "l"(x2d), "l"(w2l));
            asm("fma.rn.f32x2 %0, %1, %2, %0;" : "+l"(r) : "l"(s), "l"(nh));
            float lo, hi;
            asm("mov.b64 {%0, %1}, %2;" : "=f"(lo), "=f"(hi) : "l"(r));
            Sf[FLO + pix * 33 + lane] = lo;   // stride-33: conflict-free
            Sf[FHI + pix * 33 + lane] = hi;
        }
    }
    __syncthreads();

    // ---- store: lane = pixel, coalesced 128B STG; column LDS conflict-free ----
    #pragma unroll
    for (int k = 0; k < 8; k++) {
        int fp = w + 4 * k;
        float* o0 = out + (((long)(n * F + 2 * fp)     * HW + ho) * HW);
        float* o1 = out + (((long)(n * F + 2 * fp + 1) * HW + ho) * HW);
        #pragma unroll
        for (int half = 0; half < 2; half++) {
            int pix = half * 32 + lane;
            o0[pix] = Sf[FLO + pix * 33 + fp];
            o1[pix] = Sf[FHI + pix * 33 + fp];
        }
    }
}

extern "C" void kernel_launch(void* const* d_in, const int* in_sizes, int n_in,
                              void* d_out, int out_size) {
    const float* x = (const float*)d_in[0];
    const float* W = (const float*)d_in[1];
    float* out = (float*)d_out;

    dim3 grid(HW, 8);    // 512 CTAs
    euclid2d_kernel<<<grid, NTHR>>>(x, W, out);
}

// round 9
// speedup vs baseline: 1.0189x; 1.0189x over previous
#include <cuda_runtime.h>

typedef unsigned long long u64;

#define HW   64
#define F    64
#define D    75
#define KR   5
#define NROW 15
#define PXW  32          // pixels per CTA (half row)
#define SXW  36          // PXW + 4 halo
#define NTHR 128

// u64 offsets
#define WPU  0           // WP pairs [75][33] u64 (stride-33 pad) = 2475
#define STGU 2475        // stage [16][77] f32 = 616 u64
#define XPU  3092        // patch dup [15][36] u64 = 540  (16B aligned base)
#define W2U  3632        // 32
#define SWU  3664        // 128
#define X2U  3792        // 32 f32 = 16
#define SMEM_U64 3808    // 30464 B -> 7 CTAs/SM
// f32 aliases (over STGU+XPU, both dead by epilogue)
#define STGF (STGU * 2)  // 4950
#define FLO  4950        // [32][33] f32
#define FHI  6006        // [32][33] f32   (ends 7062 = u64 3531 < W2U*2)

__global__ __launch_bounds__(NTHR, 7)
void euclid2d_kernel(const float* __restrict__ x,
                     const float* __restrict__ W,
                     float* __restrict__ out) {
    __shared__ __align__(16) u64 S[SMEM_U64];
    float* Sf = (float*)S;

    const int tid  = threadIdx.x;
    const int lane = tid & 31;
    const int w    = tid >> 5;        // warp 0..3 -> pixels w*8..w*8+7
    const int bxh  = blockIdx.x;      // 0..1 half-row
    const int ho   = blockIdx.y;      // 0..63
    const int n    = blockIdx.z;      // 0..7

    // ---- patch tile (duplicated pairs) ----
    {
        const int y0 = ho - 2;
        const int x0 = bxh * PXW - 2;
        #pragma unroll
        for (int k = 0; k < 5; k++) {
            int i = tid + k * NTHR;            // 0..539
            if (i < NROW * SXW) {
                int row = i / SXW;
                int col = i % SXW;
                int gy = y0 + (row % KR);
                int gx = x0 + col;
                float v = 0.0f;
                if (gy >= 0 && gy < HW && gx >= 0 && gx < HW)
                    v = x[((n * 3 + (row / KR)) * HW + gy) * HW + gx];
                u64 p;
                asm("mov.b64 %0, {%1, %1};" : "=l"(p) : "f"(v));
                S[XPU + i] = p;
            }
        }
    }

    // ---- W transpose in 4 chunks of 16 filters through padded stage ----
    #pragma unroll 1
    for (int ch = 0; ch < 4; ch++) {
        const float4* src = (const float4*)(W + ch * 16 * D);
        #pragma unroll
        for (int k = 0; k < 3; k++) {
            int j = tid + k * NTHR;            // 0..299 float4
            if (j < 300) {
                float4 v = src[j];
                int b = 4 * j;
                Sf[STGF + ((b    ) / D) * 77 + (b    ) % D] = v.x;
                Sf[STGF + ((b + 1) / D) * 77 + (b + 1) % D] = v.y;
                Sf[STGF + ((b + 2) / D) * 77 + (b + 2) % D] = v.z;
                Sf[STGF + ((b + 3) / D) * 77 + (b + 3) % D] = v.w;
            }
        }
        __syncthreads();
        #pragma unroll
        for (int k = 0; k < 5; k++) {
            int idx = tid + k * NTHR;          // 0..599 : fp-major
            if (idx < 8 * D) {
                int fp_l = idx / D;
                int d    = idx % D;
                float lo = Sf[STGF + (2 * fp_l)     * 77 + d];
                float hi = Sf[STGF + (2 * fp_l + 1) * 77 + d];
                u64 p;
                asm("mov.b64 %0, {%1, %2};" : "=l"(p) : "f"(lo), "f"(hi));
                S[WPU + d * 33 + ch * 8 + fp_l] = p;
            }
        }
        __syncthreads();
    }

    // ---- x2 per pixel (4 thr/px) and w2 partials ----
    {
        const int px = tid >> 2;
        const int q  = tid & 3;
        float s = 0.0f;
        #pragma unroll
        for (int k = 0; k < 19; k++) {
            int d = q + 4 * k;
            if (d < D) {
                int row = d / KR, kw = d % KR;
                float v = Sf[(XPU + row * SXW + px + kw) * 2];
                s += v * v;
            }
        }
        s += __shfl_xor_sync(0xffffffffu, s, 1);
        s += __shfl_xor_sync(0xffffffffu, s, 2);
        if (q == 0) Sf[X2U * 2 + px] = s;
    }
    {
        int fp = tid & 31, q = tid >> 5;
        u64 a = 0ULL;
        #pragma unroll
        for (int k = 0; k < 19; k++) {
            int d = q + 4 * k;
            if (d < D) {
                u64 wv = S[WPU + d * 33 + fp];
                asm("fma.rn.f32x2 %0, %1, %1, %0;" : "+l"(a) : "l"(wv));
            }
        }
        S[SWU + q * 32 + fp] = a;
    }
    __syncthreads();
    if (tid < 32) {
        u64 a = S[SWU + tid], b = S[SWU + 32 + tid];
        u64 c = S[SWU + 64 + tid], d = S[SWU + 96 + tid];
        u64 r;
        asm("add.rn.f32x2 %0, %1, %2;" : "=l"(r) : "l"(a), "l"(b));
        asm("add.rn.f32x2 %0, %0, %1;" : "+l"(r) : "l"(c));
        asm("add.rn.f32x2 %0, %0, %1;" : "+l"(r) : "l"(d));
        S[W2U + tid] = r;
    }
    __syncthreads();

    // ---- main loop: lane = filter pair, thread = 8 pixels ----
    u64 acc[8];
    #pragma unroll
    for (int p = 0; p < 8; p++) acc[p] = 0ULL;

    #pragma unroll 1
    for (int row = 0; row < NROW; row++) {
        const ulonglong2* prow = (const ulonglong2*)&S[XPU + row * SXW + w * 8];
        ulonglong2 P2[6];
        #pragma unroll
        for (int t = 0; t < 6; t++) P2[t] = prow[t];       // broadcast LDS.128
        const u64* Pu = (const u64*)P2;                     // 12 u64
        #pragma unroll
        for (int kw = 0; kw < KR; kw++) {
            u64 wv = S[WPU + (row * KR + kw) * 33 + lane];  // conflict-free LDS.64
            #pragma unroll
            for (int p = 0; p < 8; p++)
                asm("fma.rn.f32x2 %0, %1, %2, %0;"
                    : "+l"(acc[p]) : "l"(Pu[kw + p]), "l"(wv));
        }
    }

    // ---- epilogue ----
    {
        u64 w2l = S[W2U + lane];
        u64 nh;
        { float mh = -0.5f; asm("mov.b64 %0, {%1, %1};" : "=l"(nh) : "f"(mh)); }
        float x2v[8];
        #pragma unroll
        for (int p = 0; p < 8; p++) x2v[p] = Sf[X2U * 2 + w * 8 + p];
        __syncthreads();   // patch/stage reads done -> safe to alias FLO/FHI
        #pragma unroll
        for (int p = 0; p < 8; p++) {
            int px = w * 8 + p;
            u64 x2d, s, r = acc[p];
            asm("mov.b64 %0, {%1, %1};" : "=l"(x2d) : "f"(x2v[p]));
            asm("add.rn.f32x2 %0, %1, %2;" : "=l"(s) : "l"(x2d), "l"(w2l));
            asm("fma.rn.f32x2 %0, %1, %2, %0;" : "+l"(r) : "l"(s), "l"(nh));
            float lo, hi;
            asm("mov.b64 {%0, %1}, %2;" : "=f"(lo), "=f"(hi) : "l"(r));
            Sf[FLO + px * 33 + lane] = lo;    // conflict-free
            Sf[FHI + px * 33 + lane] = hi;
        }
    }
    __syncthreads();

    // ---- store: lane = pixel -> 1 line per STG.32 ----
    #pragma unroll
    for (int k = 0; k < 8; k++) {
        int fp = w + 4 * k;
        float* o0 = out + (((long)(n * F + 2 * fp)     * HW + ho) * HW) + bxh * PXW;
        float* o1 = out + (((long)(n * F + 2 * fp + 1) * HW + ho) * HW) + bxh * PXW;
        o0[lane] = Sf[FLO + lane * 33 + fp];
        o1[lane] = Sf[FHI + lane * 33 + fp];
    }
}

extern "C" void kernel_launch(void* const* d_in, const int* in_sizes, int n_in,
                              void* d_out, int out_size) {
    const float* x = (const float*)d_in[0];
    const float* W = (const float*)d_in[1];
    float* out = (float*)d_out;

    dim3 grid(2, HW, 8);   // 1024 CTAs, single wave at 7 CTAs/SM
    euclid2d_kernel<<<grid, NTHR>>>(x, W, out);
}

// round 10
// speedup vs baseline: 1.0423x; 1.0229x over previous
#include <cuda_runtime.h>

typedef unsigned long long u64;

#define HW   64
#define F    64
#define D    75
#define KR   5
#define NROW 15
#define SXW  68          // full row + 4 halo
#define NTHR 128

// u64 offsets
#define WPU  0           // WP pairs [75][33] u64 (stride-33 pad) = 2475
#define STGU 2476        // stage [16][77] f32 = 1232 f32 = 616 u64
#define XPU  3092        // patch dup [15][68] u64 = 1020
#define W2U  4112        // 32
#define SWU  4144        // 128
#define X2U  4272        // 64 f32 = 32 u64
#define SMEM_U64 4304    // 34432 B
// f32 aliases over WP (dead after main loop)
#define STGF (STGU * 2)
#define FLO  0           // [64][33] f32 = 2112
#define FHI  2112        // [64][33] f32 (ends 4224 f32 = 2112 u64 < WPU end)

__global__ __launch_bounds__(NTHR, 4)
void euclid2d_kernel(const float* __restrict__ x,
                     const float* __restrict__ W,
                     float* __restrict__ out) {
    __shared__ __align__(16) u64 S[SMEM_U64];
    float* Sf = (float*)S;

    const int tid  = threadIdx.x;
    const int lane = tid & 31;
    const int w    = tid >> 5;        // warp 0..3 -> pixels w*16..w*16+15
    const int ho   = blockIdx.x;      // 0..63
    const int n    = blockIdx.y;      // 0..7

    // ---- patch tile (duplicated pairs), full 64-px row ----
    {
        const int y0 = ho - 2;
        #pragma unroll
        for (int k = 0; k < 8; k++) {
            int i = tid + k * NTHR;            // 0..1019
            if (i < NROW * SXW) {
                int row = i / SXW;
                int col = i % SXW;
                int gy = y0 + (row % KR);
                int gx = col - 2;
                float v = 0.0f;
                if (gy >= 0 && gy < HW && gx >= 0 && gx < HW)
                    v = x[((n * 3 + (row / KR)) * HW + gy) * HW + gx];
                u64 p;
                asm("mov.b64 %0, {%1, %1};" : "=l"(p) : "f"(v));
                S[XPU + i] = p;
            }
        }
    }

    // ---- W transpose in 4 chunks of 16 filters through padded stage ----
    #pragma unroll 1
    for (int ch = 0; ch < 4; ch++) {
        const float4* src = (const float4*)(W + ch * 16 * D);
        #pragma unroll
        for (int k = 0; k < 3; k++) {
            int j = tid + k * NTHR;            // 0..299 float4
            if (j < 300) {
                float4 v = src[j];
                int b = 4 * j;
                Sf[STGF + ((b    ) / D) * 77 + (b    ) % D] = v.x;
                Sf[STGF + ((b + 1) / D) * 77 + (b + 1) % D] = v.y;
                Sf[STGF + ((b + 2) / D) * 77 + (b + 2) % D] = v.z;
                Sf[STGF + ((b + 3) / D) * 77 + (b + 3) % D] = v.w;
            }
        }
        __syncthreads();
        #pragma unroll
        for (int k = 0; k < 5; k++) {
            int idx = tid + k * NTHR;          // 0..599 : fp-major
            if (idx < 8 * D) {
                int fp_l = idx / D;            // local filter pair 0..7
                int d    = idx % D;
                float lo = Sf[STGF + (2 * fp_l)     * 77 + d];
                float hi = Sf[STGF + (2 * fp_l + 1) * 77 + d];
                u64 p;
                asm("mov.b64 %0, {%1, %2};" : "=l"(p) : "f"(lo), "f"(hi));
                S[WPU + d * 33 + ch * 8 + fp_l] = p;
            }
        }
        __syncthreads();
    }

    // ---- x2 per pixel (2 thr/px) and w2 partials (4-way d-split) ----
    {
        const int px = tid >> 1;               // 0..63
        const int q  = tid & 1;
        float s = 0.0f;
        #pragma unroll
        for (int k = 0; k < 38; k++) {
            int d = q + 2 * k;
            if (d < D) {
                int row = d / KR, kw = d % KR;
                float v = Sf[(XPU + row * SXW + px + kw) * 2];
                s += v * v;
            }
        }
        s += __shfl_xor_sync(0xffffffffu, s, 1);
        if (q == 0) Sf[X2U * 2 + px] = s;
    }
    {
        int fp = tid & 31, q = tid >> 5;
        u64 a = 0ULL;
        #pragma unroll
        for (int k = 0; k < 19; k++) {
            int d = q + 4 * k;
            if (d < D) {
                u64 wv = S[WPU + d * 33 + fp];
                asm("fma.rn.f32x2 %0, %1, %1, %0;" : "+l"(a) : "l"(wv));
            }
        }
        S[SWU + q * 32 + fp] = a;
    }
    __syncthreads();
    if (tid < 32) {
        u64 a = S[SWU + tid], b = S[SWU + 32 + tid];
        u64 c = S[SWU + 64 + tid], d = S[SWU + 96 + tid];
        u64 r;
        asm("add.rn.f32x2 %0, %1, %2;" : "=l"(r) : "l"(a), "l"(b));
        asm("add.rn.f32x2 %0, %0, %1;" : "+l"(r) : "l"(c));
        asm("add.rn.f32x2 %0, %0, %1;" : "+l"(r) : "l"(d));
        S[W2U + tid] = r;
    }
    __syncthreads();

    // ---- main loop: lane = filter pair, thread = 16 pixels ----
    u64 acc[16];
    #pragma unroll
    for (int p = 0; p < 16; p++) acc[p] = 0ULL;

    #pragma unroll 1
    for (int row = 0; row < NROW; row++) {
        const ulonglong2* prow = (const ulonglong2*)&S[XPU + row * SXW + w * 16];
        ulonglong2 P2[10];
        #pragma unroll
        for (int t = 0; t < 10; t++) P2[t] = prow[t];       // broadcast LDS.128
        const u64* Pu = (const u64*)P2;                      // 20 u64
        #pragma unroll
        for (int kw = 0; kw < KR; kw++) {
            u64 wv = S[WPU + (row * KR + kw) * 33 + lane];   // conflict-free LDS.64
            #pragma unroll
            for (int p = 0; p < 16; p++)
                asm("fma.rn.f32x2 %0, %1, %2, %0;"
                    : "+l"(acc[p]) : "l"(Pu[kw + p]), "l"(wv));
        }
    }

    // ---- epilogue: res = acc - 0.5*(x2+w2); FLO/FHI alias WP ----
    {
        u64 w2l = S[W2U + lane];
        u64 nh;
        { float mh = -0.5f; asm("mov.b64 %0, {%1, %1};" : "=l"(nh) : "f"(mh)); }
        float x2v[16];
        #pragma unroll
        for (int p = 0; p < 16; p++) x2v[p] = Sf[X2U * 2 + w * 16 + p];
        __syncthreads();   // all WP reads complete before aliasing
        #pragma unroll
        for (int p = 0; p < 16; p++) {
            int px = w * 16 + p;
            u64 x2d, s, r = acc[p];
            asm("mov.b64 %0, {%1, %1};" : "=l"(x2d) : "f"(x2v[p]));
            asm("add.rn.f32x2 %0, %1, %2;" : "=l"(s) : "l"(x2d), "l"(w2l));
            asm("fma.rn.f32x2 %0, %1, %2, %0;" : "+l"(r) : "l"(s), "l"(nh));
            float lo, hi;
            asm("mov.b64 {%0, %1}, %2;" : "=f"(lo), "=f"(hi) : "l"(r));
            Sf[FLO + px * 33 + lane] = lo;    // stride-33: conflict-free
            Sf[FHI + px * 33 + lane] = hi;
        }
    }
    __syncthreads();

    // ---- store: lane = pixel -> contiguous 128B runs ----
    #pragma unroll
    for (int k = 0; k < 8; k++) {
        int fp = w + 4 * k;
        float* o0 = out + (((long)(n * F + 2 * fp)     * HW + ho) * HW);
        float* o1 = out + (((long)(n * F + 2 * fp + 1) * HW + ho) * HW);
        #pragma unroll
        for (int half = 0; half < 2; half++) {
            int px = half * 32 + lane;
            o0[px] = Sf[FLO + px * 33 + fp];
            o1[px] = Sf[FHI + px * 33 + fp];
        }
    }
}

extern "C" void kernel_launch(void* const* d_in, const int* in_sizes, int n_in,
                              void* d_out, int out_size) {
    const float* x = (const float*)d_in[0];
    const float* W = (const float*)d_in[1];
    float* out = (float*)d_out;

    dim3 grid(HW, 8);    // 512 CTAs
    euclid2d_kernel<<<grid, NTHR>>>(x, W, out);
}

// round 11
// speedup vs baseline: 1.1212x; 1.0758x over previous
#include <cuda_runtime.h>

typedef unsigned long long u64;

#define HW   64
#define F    64
#define D    75
#define KR   5
#define NROW 15
#define SXW  68          // full row + 4 halo
#define NTHR 128

// u64 offsets
#define WPU  0           // WP pairs [75][33] u64 (stride-33 pad) = 2475
#define XPU  2476        // patch dup [15][68] u64 = 1020 (16B-aligned base)
#define SWU  3496        // w2 partials [4][32] u64 = 128
#define X2U  3624        // x2: 64 f32 = 32 u64
#define SMEM_U64 3656    // 29248 B
// f32 aliases over WP (dead after main loop)
#define FLO  0           // [64][33] f32 = 2112
#define FHI  2112        // [64][33] f32 (ends at f32 4224 = u64 2112 < 2475)

__global__ __launch_bounds__(NTHR, 4)
void euclid2d_kernel(const float* __restrict__ x,
                     const float* __restrict__ W,
                     float* __restrict__ out) {
    __shared__ __align__(16) u64 S[SMEM_U64];
    float* Sf = (float*)S;

    const int tid  = threadIdx.x;
    const int lane = tid & 31;
    const int w    = tid >> 5;        // warp 0..3 -> pixels w*16..w*16+15
    const int ho   = blockIdx.x;      // 0..63
    const int n    = blockIdx.y;      // 0..7

    // ---- patch tile (duplicated pairs), full 64-px row ----
    {
        const int y0 = ho - 2;
        #pragma unroll
        for (int k = 0; k < 8; k++) {
            int i = tid + k * NTHR;            // 0..1019
            if (i < NROW * SXW) {
                int row = i / SXW;
                int col = i % SXW;
                int gy = y0 + (row % KR);
                int gx = col - 2;
                float v = 0.0f;
                if (gy >= 0 && gy < HW && gx >= 0 && gx < HW)
                    v = x[((n * 3 + (row / KR)) * HW + gy) * HW + gx];
                u64 p;
                asm("mov.b64 %0, {%1, %1};" : "=l"(p) : "f"(v));
                S[XPU + i] = p;
            }
        }
    }

    // ---- direct W transpose: lane = d -> coalesced LDG, conflict-free STS.64 ----
    // tasks t = 0..95: fp = t & 31, dblk = t >> 5; warp w takes t ≡ w (mod 4)
    #pragma unroll
    for (int it = 0; it < 24; it++) {
        int t    = w + 4 * it;
        int fp   = t & 31;
        int dblk = t >> 5;
        int d    = dblk * 32 + lane;
        if (d < D) {
            float lo = W[(2 * fp)     * D + d];   // lane-consecutive
            float hi = W[(2 * fp + 1) * D + d];   // lane-consecutive
            u64 p;
            asm("mov.b64 %0, {%1, %2};" : "=l"(p) : "f"(lo), "f"(hi));
            S[WPU + d * 33 + fp] = p;             // stride-33: conflict-free
        }
    }
    __syncthreads();   // barrier 1: WP + patch ready

    // ---- x2 partials (2 thr/px, shfl) and w2 partials (4-way d-split) ----
    {
        const int px = tid >> 1;               // 0..63
        const int q  = tid & 1;
        float s = 0.0f;
        #pragma unroll
        for (int k = 0; k < 38; k++) {
            int d = q + 2 * k;
            if (d < D) {
                int row = d / KR, kw = d % KR;
                float v = Sf[(XPU + row * SXW + px + kw) * 2];
                s += v * v;
            }
        }
        s += __shfl_xor_sync(0xffffffffu, s, 1);
        if (q == 0) Sf[X2U * 2 + px] = s;
    }
    {
        int fp = tid & 31, q = tid >> 5;
        u64 a = 0ULL;
        #pragma unroll
        for (int k = 0; k < 19; k++) {
            int d = q + 4 * k;
            if (d < D) {
                u64 wv = S[WPU + d * 33 + fp];
                asm("fma.rn.f32x2 %0, %1, %1, %0;" : "+l"(a) : "l"(wv));
            }
        }
        S[SWU + q * 32 + fp] = a;
    }
    __syncthreads();   // barrier 2: partials ready

    // ---- main loop: lane = filter pair, thread = 16 pixels (FULL unroll) ----
    u64 acc[16];
    #pragma unroll
    for (int p = 0; p < 16; p++) acc[p] = 0ULL;

    #pragma unroll
    for (int row = 0; row < NROW; row++) {
        const ulonglong2* prow = (const ulonglong2*)&S[XPU + row * SXW + w * 16];
        ulonglong2 P2[10];
        #pragma unroll
        for (int t = 0; t < 10; t++) P2[t] = prow[t];       // broadcast LDS.128
        const u64* Pu = (const u64*)P2;                      // 20 u64
        #pragma unroll
        for (int kw = 0; kw < KR; kw++) {
            u64 wv = S[WPU + (row * KR + kw) * 33 + lane];   // conflict-free LDS.64
            #pragma unroll
            for (int p = 0; p < 16; p++)
                asm("fma.rn.f32x2 %0, %1, %2, %0;"
                    : "+l"(acc[p]) : "l"(Pu[kw + p]), "l"(wv));
        }
    }

    // ---- epilogue: w2 from partials (no extra barrier), res, padded transpose ----
    {
        u64 a0 = S[SWU + lane],      a1 = S[SWU + 32 + lane];
        u64 a2 = S[SWU + 64 + lane], a3 = S[SWU + 96 + lane];
        u64 w2l;
        asm("add.rn.f32x2 %0, %1, %2;" : "=l"(w2l) : "l"(a0), "l"(a1));
        asm("add.rn.f32x2 %0, %0, %1;" : "+l"(w2l) : "l"(a2));
        asm("add.rn.f32x2 %0, %0, %1;" : "+l"(w2l) : "l"(a3));
        u64 nh;
        { float mh = -0.5f; asm("mov.b64 %0, {%1, %1};" : "=l"(nh) : "f"(mh)); }
        float x2v[16];
        #pragma unroll
        for (int p = 0; p < 16; p++) x2v[p] = Sf[X2U * 2 + w * 16 + p];
        __syncthreads();   // barrier 3: all WP/partial reads done before aliasing
        #pragma unroll
        for (int p = 0; p < 16; p++) {
            int px = w * 16 + p;
            u64 x2d, s, r = acc[p];
            asm("mov.b64 %0, {%1, %1};" : "=l"(x2d) : "f"(x2v[p]));
            asm("add.rn.f32x2 %0, %1, %2;" : "=l"(s) : "l"(x2d), "l"(w2l));
            asm("fma.rn.f32x2 %0, %1, %2, %0;" : "+l"(r) : "l"(s), "l"(nh));
            float lo, hi;
            asm("mov.b64 {%0, %1}, %2;" : "=f"(lo), "=f"(hi) : "l"(r));
            Sf[FLO + px * 33 + lane] = lo;    // conflict-free
            Sf[FHI + px * 33 + lane] = hi;
        }
    }
    __syncthreads();   // barrier 4: transpose buffer ready

    // ---- store: lane = pixel -> contiguous 128B runs ----
    #pragma unroll
    for (int k = 0; k < 8; k++) {
        int fp = w + 4 * k;
        float* o0 = out + (((long)(n * F + 2 * fp)     * HW + ho) * HW);
        float* o1 = out + (((long)(n * F + 2 * fp + 1) * HW + ho) * HW);
        #pragma unroll
        for (int half = 0; half < 2; half++) {
            int px = half * 32 + lane;
            o0[px] = Sf[FLO + px * 33 + fp];
            o1[px] = Sf[FHI + px * 33 + fp];
        }
    }
}

extern "C" void kernel_launch(void* const* d_in, const int* in_sizes, int n_in,
                              void* d_out, int out_size) {
    const float* x = (const float*)d_in[0];
    const float* W = (const float*)d_in[1];
    float* out = (float*)d_out;

    dim3 grid(HW, 8);    // 512 CTAs
    euclid2d_kernel<<<grid, NTHR>>>(x, W, out);
}